// round 11
// baseline (speedup 1.0000x reference)
#include <cuda_runtime.h>
#include <cuda_bf16.h>

// Gemma4VisionPooler: 2x2 segment-mean pool (B=16, L=4096 -> 1024, H=1152) * sqrt(H)
// R8: pool_kernel byte-identical (56.8us @ 6.16TB/s = mixed-stream roofline).
// Scatter widened to 64 co-resident blocks (4/batch) with two global spin
// barriers (all 64 blocks fit in wave 1 -> deadlock-free). Barrier counters
// are reset by the pool kernel, keeping every graph replay deterministic.

#define BATCH  16
#define LIN    4096
#define HID    1152
#define OUTLEN 1024
#define KPOOL  2          // sqrt(LIN/OUTLEN)
#define SLOTS  4          // k^2 rows per segment
#define H4     (HID / 4)  // 288 float4 per row
#define NSEG   (BATCH * OUTLEN)

#define SBLOCKS   64      // scatter blocks (must all fit in one wave: 64 < 148)
#define SPB       4       // scatter blocks per batch
#define ROWS_PB   (LIN / SPB)     // 1024 rows per block
#define SEGS_PB   (OUTLEN / SPB)  // 256 segments reset per block
#define STH       512     // scatter threads per block

// Scratch (allocation-free rule: __device__ globals; zero-initialized at load)
__device__ int  g_cnt[NSEG];     // 1 if any row maps to segment -> mask
__device__ int  g_vcnt[NSEG];    // valid (non-padded) slot cursor
__device__ int4 g_idx4[NSEG];    // packed absolute row ids, -1 = empty
__device__ int  g_is32;          // 1 if positions are int32
__device__ int  g_bmax[BATCH];   // per-batch max clamped x
__device__ int  g_done1;         // barrier 1 arrivals (reset by pool_kernel)
__device__ int  g_done2;         // barrier 2 arrivals (reset by pool_kernel)

// ---------------------------------------------------------------------------
// Index build. 64 blocks x 512 threads; block = (batch b, quarter q).
// ---------------------------------------------------------------------------
__global__ void __launch_bounds__(STH) scatter_kernel(
    const int* __restrict__ p32,
    const unsigned char* __restrict__ pad)
{
    const int b   = blockIdx.x / SPB;
    const int q   = blockIdx.x % SPB;
    const int tid = threadIdx.x;

    __shared__ int sh_is32;
    __shared__ int sh_max;
    __shared__ int sh_blkmax;
    if (tid == 0) sh_blkmax = 0;

    // ---- phase 1a: reset this block's quarter of its batch's scratch
    for (int s = q * SEGS_PB + tid; s < (q + 1) * SEGS_PB; s += STH) {
        const int bs = b * OUTLEN + s;
        g_cnt[bs]  = 0;
        g_vcnt[bs] = 0;
        g_idx4[bs] = make_int4(-1, -1, -1, -1);
    }

    // dtype detect over this block's slice of the first 2*B*L words (in-bounds
    // for both dtypes). int64: odd words are high words (0/-1). int32: odd
    // words are y coords, somewhere > 0.
    {
        const int words_pb = (BATCH * LIN * 2) / SBLOCKS;   // 2048
        const long long w0 = (long long)blockIdx.x * words_pb;
        int found = 0;
        for (int i = tid * 2 + 1; i < words_pb; i += STH * 2)
            if (p32[w0 + i] > 0) found = 1;
        found = __syncthreads_or(found);
        if (tid == 0) {
            if (found) atomicOr(&g_is32, 1);
            __threadfence();
            atomicAdd(&g_done1, 1);
            // spin: all 64 blocks co-resident in wave 1 -> guaranteed progress
            while (*((volatile int*)&g_done1) < SBLOCKS) { }
            __threadfence();
            sh_is32 = *((volatile int*)&g_is32);
        }
    }
    __syncthreads();
    const int is32 = sh_is32;

    // ---- phase 1b: dtype-aware max clamped x over this block's rows
    {
        int lmax = 0;
        for (int l = q * ROWS_PB + tid; l < (q + 1) * ROWS_PB; l += STH) {
            int xi;
            if (is32) {
                xi = p32[((long long)b * LIN + l) * 2];
            } else {
                const long long w = ((long long)b * LIN + l) * 4;
                int xlo = p32[w + 0], xhi = p32[w + 1];
                xi = (xhi < 0) ? 0 : xlo;
            }
            if (xi < 0) xi = 0;
            lmax = max(lmax, xi);
        }
        atomicMax(&sh_blkmax, lmax);   // smem atomic
        __syncthreads();
        if (tid == 0) {
            atomicMax(&g_bmax[b], sh_blkmax);   // 64 global atomics total
            __threadfence();
            atomicAdd(&g_done2, 1);
            while (*((volatile int*)&g_done2) < SBLOCKS) { }
            __threadfence();
            sh_max = *((volatile int*)&g_bmax[b]);
        }
    }
    __syncthreads();
    const int wseg = (sh_max + 1) / KPOOL;

    // ---- phase 2: decode + scatter this block's rows (positions L2-hot)
    for (int l = q * ROWS_PB + tid; l < (q + 1) * ROWS_PB; l += STH) {
        int xi, yi;
        if (is32) {
            const long long w = ((long long)b * LIN + l) * 2;
            xi = p32[w + 0];
            yi = p32[w + 1];
        } else {
            const long long w = ((long long)b * LIN + l) * 4;
            int xlo = p32[w + 0], xhi = p32[w + 1];
            int ylo = p32[w + 2], yhi = p32[w + 3];
            xi = (xhi < 0) ? -1 : xlo;
            yi = (yhi < 0) ? -1 : ylo;
        }
        if (xi < 0) xi = 0;
        if (yi < 0) yi = 0;
        int seg = xi / KPOOL + wseg * (yi / KPOOL);
        if (seg < 0) seg = 0;
        if (seg >= OUTLEN) seg = OUTLEN - 1;   // never corrupt scratch
        const int bs = b * OUTLEN + seg;

        g_cnt[bs] = 1;                         // racing stores of 1: benign

        if (!pad[(long long)b * LIN + l]) {    // only non-padded rows contribute
            int slot = atomicAdd(&g_vcnt[bs], 1);
            if (slot < SLOTS)
                ((int*)&g_idx4[bs])[slot] = b * LIN + l;  // absolute row id
        }
    }
}

// ---------------------------------------------------------------------------
// Gather + mean + scale. One block per (batch, segment), 288 threads, each
// thread owns one float4 column. Single LDG.128 of the packed index, then 4
// independent predicated streaming loads. At HBM roofline -- do not touch.
// Also resets scatter's barrier state for the next graph replay (this kernel
// is stream-ordered between consecutive scatter launches).
// ---------------------------------------------------------------------------
__global__ void __launch_bounds__(H4) pool_kernel(
    const float4* __restrict__ in,
    float4* __restrict__ out,
    float* __restrict__ mask_out)
{
    const int bs  = blockIdx.x;          // b * OUTLEN + seg
    const int tid = threadIdx.x;

    // reset cross-launch barrier/reduction state for the next replay
    if (tid == 0) {
        if (bs == 0) { g_done1 = 0; g_done2 = 0; g_is32 = 0; }
        if (bs < BATCH) g_bmax[bs] = 0;
    }

    const int4 idx = g_idx4[bs];         // one LDG.128, uniform across block

    float4 acc = make_float4(0.f, 0.f, 0.f, 0.f);
    float4 v0, v1, v2, v3;
    const bool p0 = idx.x >= 0, p1 = idx.y >= 0, p2 = idx.z >= 0, p3 = idx.w >= 0;
    if (p0) v0 = __ldcs(&in[(long long)idx.x * H4 + tid]);
    if (p1) v1 = __ldcs(&in[(long long)idx.y * H4 + tid]);
    if (p2) v2 = __ldcs(&in[(long long)idx.z * H4 + tid]);
    if (p3) v3 = __ldcs(&in[(long long)idx.w * H4 + tid]);
    if (p0) { acc.x += v0.x; acc.y += v0.y; acc.z += v0.z; acc.w += v0.w; }
    if (p1) { acc.x += v1.x; acc.y += v1.y; acc.z += v1.z; acc.w += v1.w; }
    if (p2) { acc.x += v2.x; acc.y += v2.y; acc.z += v2.z; acc.w += v2.w; }
    if (p3) { acc.x += v3.x; acc.y += v3.y; acc.z += v3.z; acc.w += v3.w; }

    // pooled = sum / k^2, then * sqrt(H) :  sqrt(1152)/4
    const float SCALE = 8.4852813742385702928f;
    acc.x *= SCALE; acc.y *= SCALE; acc.z *= SCALE; acc.w *= SCALE;

    __stcs(&out[(long long)bs * H4 + tid], acc);

    if (mask_out != nullptr && tid == 0)
        mask_out[bs] = (g_cnt[bs] > 0) ? 1.0f : 0.0f;
}

// ---------------------------------------------------------------------------
extern "C" void kernel_launch(void* const* d_in, const int* in_sizes, int n_in,
                              void* d_out, int out_size)
{
    const float*         hs  = (const float*)d_in[0];          // [B, L, H] f32
    const int*           pos = (const int*)d_in[1];            // [B, L, 2] i32 or i64
    const unsigned char* pad = (const unsigned char*)d_in[2];  // [B, L] bool

    float* out = (float*)d_out;

    const long long hs_elems = (long long)BATCH * OUTLEN * HID;
    float* mask_out = nullptr;
    if ((long long)out_size >= hs_elems + (long long)BATCH * OUTLEN)
        mask_out = out + hs_elems;

    scatter_kernel<<<SBLOCKS, STH>>>(pos, pad);
    pool_kernel<<<NSEG, H4>>>((const float4*)hs, (float4*)out, mask_out);
}